// round 2
// baseline (speedup 1.0000x reference)
#include <cuda_runtime.h>
#include <math.h>
#include <stdint.h>

// Problem constants (fixed by the reference setup)
#define NB   2048
#define NC   9605
#define NL   20
#define MAXE 4096
#define BDIM 256

// Scratch (no allocations allowed)
__device__ int           d_cls[MAXE];
__device__ unsigned char d_grp[MAXE];
__device__ int           d_cnt;
__device__ int           d_hist[4];
__device__ int           d_mode;   // 0 = uint8, 1 = int32, 2 = float32

__global__ void zero_kernel(float* out) {
    if (threadIdx.x == 0) {
        d_cnt = 0; out[0] = 0.0f;
        d_hist[0] = d_hist[1] = d_hist[2] = d_hist[3] = 0;
        d_mode = 0;
    }
}

// Probe first NL*NC BYTES (safe under every candidate dtype width) and
// histogram nonzero bytes by (offset mod 4) to infer the mask dtype.
__global__ void detect_kernel(const unsigned char* __restrict__ raw) {
    int local[4] = {0, 0, 0, 0};
    int total = NL * NC;
    for (int i = blockIdx.x * blockDim.x + threadIdx.x; i < total;
         i += gridDim.x * blockDim.x) {
        if (raw[i]) local[i & 3]++;
    }
#pragma unroll
    for (int k = 0; k < 4; ++k)
        if (local[k]) atomicAdd(&d_hist[k], local[k]);
}

__global__ void decide_kernel() {
    if (threadIdx.x == 0) {
        int h0 = d_hist[0], h1 = d_hist[1], h2 = d_hist[2], h3 = d_hist[3];
        if (h0 > 0 && h1 == 0 && h2 == 0 && h3 == 0)      d_mode = 1; // int32 0/1
        else if (h0 == 0 && h1 == 0 && (h2 > 0 || h3 > 0)) d_mode = 2; // float32 0/1
        else                                               d_mode = 0; // uint8 bool
    }
}

// Compact group_mask [L, C] into a (class, group) entry list, honoring d_mode.
__global__ void build_kernel(const void* __restrict__ maskv) {
    const int mode = d_mode;
    const unsigned char* m8  = (const unsigned char*)maskv;
    const int*           m32 = (const int*)maskv;
    const float*         mf  = (const float*)maskv;
    int total = NL * NC;
    for (int i = blockIdx.x * blockDim.x + threadIdx.x; i < total;
         i += gridDim.x * blockDim.x) {
        bool t;
        if (mode == 1)      t = (m32[i] != 0);
        else if (mode == 2) t = (mf[i] != 0.0f);
        else                t = (m8[i] != 0);
        if (t) {
            int p = atomicAdd(&d_cnt, 1);
            if (p < MAXE) {
                d_cls[p] = i % NC;
                d_grp[p] = (unsigned char)(i / NC);
            }
        }
    }
}

__device__ __forceinline__ float sigmoidf_(float v) {
    return 1.0f / (1.0f + expf(-v));
}

// our_rank_loss with ALPHA1=0.05, ALPHA2=2, ALPHA3=10
__device__ __forceinline__ float rankl(float x1, float x2) {
    float d = x2 - x1 + 0.05f;
    float s = 1.0f / (1.0f + expf(-10.0f * d));
    return (d > 0.0f) ? 2.0f * s : s;
}

// Order-preserving encode for float -> unsigned (for shared atomicMax)
__device__ __forceinline__ unsigned fenc(float v) {
    unsigned u = __float_as_uint(v);
    return (u & 0x80000000u) ? ~u : (u | 0x80000000u);
}
__device__ __forceinline__ float fdec(unsigned u) {
    return (u & 0x80000000u) ? __uint_as_float(u ^ 0x80000000u)
                             : __uint_as_float(~u);
}

__global__ void __launch_bounds__(BDIM)
loss_kernel(const float* __restrict__ x,
            const int*   __restrict__ y,
            const int*   __restrict__ yn,
            float*       __restrict__ out) {
    const int b   = blockIdx.x;
    const int tid = threadIdx.x;
    const float* xr = x + (size_t)b * NC;

    // ---- per-thread top-11 over strided row elements (raw x; sigmoid is monotone)
    float t[11];
#pragma unroll
    for (int j = 0; j < 11; ++j) t[j] = -3.0e38f;

    for (int c = tid; c < NC; c += BDIM) {
        float v = __ldg(xr + c);
        if (v > t[10]) {
            t[10] = v;
#pragma unroll
            for (int j = 10; j > 0; --j) {
                float a = t[j - 1], bb = t[j];
                if (bb > a) { t[j - 1] = bb; t[j] = a; }
            }
        }
    }

    __shared__ float    swv[BDIM / 32];
    __shared__ int      swi[BDIM / 32];
    __shared__ float    s_val;
    __shared__ int      s_win;
    __shared__ unsigned s_gmax[NL];
    __shared__ int      s_act[NL];
    __shared__ int      s_an[NL];

    if (tid < NL) { s_gmax[tid] = 0u; s_act[tid] = 0; s_an[tid] = 0; }

    // ---- 11 rounds of block argmax extraction -> 11th-largest value of the row
    const int lane = tid & 31, wid = tid >> 5;
    int   p   = 0;
    float v11 = -3.0e38f;
    for (int iter = 0; iter < 11; ++iter) {
        float v   = (p < 11) ? t[p] : -3.4e38f;
        int   idx = tid;
#pragma unroll
        for (int o = 16; o > 0; o >>= 1) {
            float ov = __shfl_down_sync(0xffffffffu, v, o);
            int   oi = __shfl_down_sync(0xffffffffu, idx, o);
            if (ov > v) { v = ov; idx = oi; }
        }
        if (lane == 0) { swv[wid] = v; swi[wid] = idx; }
        __syncthreads();
        if (tid == 0) {
            float bv = swv[0]; int bi = swi[0];
#pragma unroll
            for (int w = 1; w < BDIM / 32; ++w)
                if (swv[w] > bv) { bv = swv[w]; bi = swi[w]; }
            s_val = bv; s_win = bi;
        }
        __syncthreads();
        if (tid == s_win) ++p;
        v11 = s_val;
    }
    __syncthreads();

    // thres = max(sigmoid(11th largest x), ALPHA_OTHER=0.5)
    const float thres = fmaxf(sigmoidf_(v11), 0.5f);

    // ---- gather the ~1000 whitelist classes; per-group max(x) + activity flags
    int ne = d_cnt; if (ne > MAXE) ne = MAXE;
    const int* yr  = y  + (size_t)b * NC;
    const int* ynr = yn + (size_t)b * NC;
    for (int i = tid; i < ne; i += BDIM) {
        int c = d_cls[i];
        int l = (int)d_grp[i];
        atomicMax(&s_gmax[l], fenc(__ldg(xr + c)));
        if (__ldg(yr  + c)) atomicOr(&s_act[l], 1);
        if (__ldg(ynr + c)) atomicOr(&s_an[l],  1);
    }
    __syncthreads();

    if (tid == 0) {
        float gs[NL];
        float umax = 0.0f;
#pragma unroll
        for (int l = 0; l < NL; ++l) {
            gs[l] = sigmoidf_(fdec(s_gmax[l]));
            umax  = fmaxf(umax, gs[l]);
        }
        int g = -1;
#pragma unroll
        for (int l = 0; l < NL; ++l)
            if (g < 0 && s_act[l]) g = l;

        float imax = 0.0f, ineg = 0.0f;
#pragma unroll
        for (int l = 0; l < NL; ++l) {
            if (l != g)  imax = fmaxf(imax, gs[l]);
            if (s_an[l]) ineg = fmaxf(ineg, gs[l]);
        }

        float loss;
        if (g < 0) {
            // branch A: no gt whitelist group
            loss = 0.5f * rankl(thres, umax) + 0.5f * rankl(thres, ineg);
        } else {
            // branch B
            loss = rankl(gs[g], thres);
            if (imax > 0.0f) loss += 0.5f * rankl(thres, imax);
            loss += 0.5f * ((ineg > 0.0f) ? rankl(thres, ineg)
                                          : rankl(thres, imax));
        }
        atomicAdd(out, loss);
    }
}

extern "C" void kernel_launch(void* const* d_in, const int* in_sizes, int n_in,
                              void* d_out, int out_size) {
    const float* x    = (const float*)d_in[0];
    const int*   y    = (const int*)d_in[1];
    const int*   yn   = (const int*)d_in[2];
    const void*  mask = (const void*)d_in[3];
    float*       out  = (float*)d_out;

    zero_kernel<<<1, 32>>>(out);
    detect_kernel<<<64, 256>>>((const unsigned char*)mask);
    decide_kernel<<<1, 32>>>();
    build_kernel<<<192, 256>>>(mask);
    loss_kernel<<<NB, BDIM>>>(x, y, yn, out);
}

// round 3
// speedup vs baseline: 1.4336x; 1.4336x over previous
#include <cuda_runtime.h>
#include <math.h>
#include <stdint.h>
#include <float.h>

#define NB   2048
#define NC   9605
#define NL   20
#define MAXE 4096
#define BDIM 256
#define CAP  2048          // shared candidate buffer
#define T1   2.5f          // expected ~60 candidates for N(0,1)
#define T2   1.0f          // expected ~1500 candidates

// Scratch (no allocations allowed)
__device__ int           d_cls[MAXE];
__device__ unsigned char d_grp[MAXE];
__device__ int           d_cnt;
__device__ int           d_hist[4];
__device__ int           d_mode;       // 0 = uint8, 1 = int32, 2 = float32
__device__ float         d_loss[NB];

__global__ void zero_kernel() {
    if (threadIdx.x == 0) {
        d_cnt = 0;
        d_hist[0] = d_hist[1] = d_hist[2] = d_hist[3] = 0;
        d_mode = 0;
    }
}

// Probe first NL*NC BYTES (safe under every candidate dtype width); histogram
// nonzero bytes by (offset mod 4) to infer the mask dtype.
__global__ void detect_kernel(const unsigned char* __restrict__ raw) {
    int local[4] = {0, 0, 0, 0};
    int total = NL * NC;
    for (int i = blockIdx.x * blockDim.x + threadIdx.x; i < total;
         i += gridDim.x * blockDim.x) {
        if (raw[i]) local[i & 3]++;
    }
#pragma unroll
    for (int k = 0; k < 4; ++k)
        if (local[k]) atomicAdd(&d_hist[k], local[k]);
}

__global__ void decide_kernel() {
    if (threadIdx.x == 0) {
        int h0 = d_hist[0], h1 = d_hist[1], h2 = d_hist[2], h3 = d_hist[3];
        if (h0 > 0 && h1 == 0 && h2 == 0 && h3 == 0)       d_mode = 1; // int32
        else if (h0 == 0 && h1 == 0 && (h2 > 0 || h3 > 0)) d_mode = 2; // float32
        else                                               d_mode = 0; // uint8
    }
}

// Compact group_mask [L, C] into a (class, group) list, honoring d_mode.
__global__ void build_kernel(const void* __restrict__ maskv) {
    const int mode = d_mode;
    const unsigned char* m8  = (const unsigned char*)maskv;
    const int*           m32 = (const int*)maskv;
    const float*         mf  = (const float*)maskv;
    int total = NL * NC;
    for (int i = blockIdx.x * blockDim.x + threadIdx.x; i < total;
         i += gridDim.x * blockDim.x) {
        bool t;
        if (mode == 1)      t = (m32[i] != 0);
        else if (mode == 2) t = (mf[i] != 0.0f);
        else                t = (m8[i] != 0);
        if (t) {
            int p = atomicAdd(&d_cnt, 1);
            if (p < MAXE) {
                d_cls[p] = i % NC;
                d_grp[p] = (unsigned char)(i / NC);
            }
        }
    }
}

__device__ __forceinline__ float sigmoidf_(float v) {
    return 1.0f / (1.0f + expf(-v));
}

__device__ __forceinline__ float rankl(float x1, float x2) {
    float d = x2 - x1 + 0.05f;
    float s = 1.0f / (1.0f + expf(-10.0f * d));
    return (d > 0.0f) ? 2.0f * s : s;
}

__device__ __forceinline__ unsigned fenc(float v) {
    unsigned u = __float_as_uint(v);
    return (u & 0x80000000u) ? ~u : (u | 0x80000000u);
}
__device__ __forceinline__ float fdec(unsigned u) {
    return (u & 0x80000000u) ? __uint_as_float(u ^ 0x80000000u)
                             : __uint_as_float(~u);
}

__global__ void __launch_bounds__(BDIM)
loss_kernel(const float* __restrict__ x,
            const int*   __restrict__ y,
            const int*   __restrict__ yn) {
    const int b   = blockIdx.x;
    const int tid = threadIdx.x;
    const float* xr = x + (size_t)b * NC;

    __shared__ float    s_cand[CAP];
    __shared__ int      s_cnt;
    __shared__ float    s_v11;
    __shared__ unsigned s_gmax[NL];
    __shared__ int      s_act[NL];
    __shared__ int      s_an[NL];

    if (tid == 0) s_cnt = 0;
    if (tid < NL) { s_gmax[tid] = 0u; s_act[tid] = 0; s_an[tid] = 0; }
    __syncthreads();

    // ---- pass 1: branch-light scan, collect candidates > T1 (4-way unrolled,
    // independent loads for MLP; pushes are rare so divergence is negligible)
    {
        int c = tid;
        for (; c + 3 * BDIM < NC; c += 4 * BDIM) {
            float v0 = __ldg(xr + c);
            float v1 = __ldg(xr + c + BDIM);
            float v2 = __ldg(xr + c + 2 * BDIM);
            float v3 = __ldg(xr + c + 3 * BDIM);
            if (v0 > T1) { int p = atomicAdd(&s_cnt, 1); if (p < CAP) s_cand[p] = v0; }
            if (v1 > T1) { int p = atomicAdd(&s_cnt, 1); if (p < CAP) s_cand[p] = v1; }
            if (v2 > T1) { int p = atomicAdd(&s_cnt, 1); if (p < CAP) s_cand[p] = v2; }
            if (v3 > T1) { int p = atomicAdd(&s_cnt, 1); if (p < CAP) s_cand[p] = v3; }
        }
        for (; c < NC; c += BDIM) {
            float v = __ldg(xr + c);
            if (v > T1) { int p = atomicAdd(&s_cnt, 1); if (p < CAP) s_cand[p] = v; }
        }
    }
    __syncthreads();

    int cnt = s_cnt;
    // ---- tier 2 fallback: re-scan (row is L1-hot) with a lower threshold
    if (cnt < 11 || cnt > CAP) {
        __syncthreads();
        if (tid == 0) s_cnt = 0;
        __syncthreads();
        for (int c = tid; c < NC; c += BDIM) {
            float v = __ldg(xr + c);
            if (v > T2) { int p = atomicAdd(&s_cnt, 1); if (p < CAP) s_cand[p] = v; }
        }
        __syncthreads();
        cnt = s_cnt;
    }

    float v11;
    if (cnt >= 11 && cnt <= CAP) {
        // exact 11th-largest via rank counting over candidates
        for (int i = tid; i < cnt; i += BDIM) {
            float vi = s_cand[i];
            int rank = 0;
            for (int j = 0; j < cnt; ++j) {
                float vj = s_cand[j];
                rank += (vj > vi) || (vj == vi && j < i);
            }
            if (rank == 10) s_v11 = vi;
        }
        __syncthreads();
        v11 = s_v11;
    } else {
        // ---- tier 3: exact slow path (unused for the bench distribution)
        float t[11];
#pragma unroll
        for (int j = 0; j < 11; ++j) t[j] = -3.0e38f;
        for (int c = tid; c < NC; c += BDIM) {
            float v = __ldg(xr + c);
            if (v > t[10]) {
                t[10] = v;
#pragma unroll
                for (int j = 10; j > 0; --j) {
                    float a = t[j - 1], bb = t[j];
                    if (bb > a) { t[j - 1] = bb; t[j] = a; }
                }
            }
        }
        __shared__ float swv[BDIM / 32];
        __shared__ int   swi[BDIM / 32];
        __shared__ float s_val;
        __shared__ int   s_win;
        const int lane = tid & 31, wid = tid >> 5;
        int p = 0;
        v11 = -3.0e38f;
        for (int iter = 0; iter < 11; ++iter) {
            float v   = (p < 11) ? t[p] : -3.4e38f;
            int   idx = tid;
#pragma unroll
            for (int o = 16; o > 0; o >>= 1) {
                float ov = __shfl_down_sync(0xffffffffu, v, o);
                int   oi = __shfl_down_sync(0xffffffffu, idx, o);
                if (ov > v) { v = ov; idx = oi; }
            }
            if (lane == 0) { swv[wid] = v; swi[wid] = idx; }
            __syncthreads();
            if (tid == 0) {
                float bv = swv[0]; int bi = swi[0];
#pragma unroll
                for (int w = 1; w < BDIM / 32; ++w)
                    if (swv[w] > bv) { bv = swv[w]; bi = swi[w]; }
                s_val = bv; s_win = bi;
            }
            __syncthreads();
            if (tid == s_win) ++p;
            v11 = s_val;
            __syncthreads();
        }
    }

    const float thres = fmaxf(sigmoidf_(v11), 0.5f);

    // ---- gather ~1000 whitelist classes: per-group max(x) + activity flags
    int ne = d_cnt; if (ne > MAXE) ne = MAXE;
    const int* yr  = y  + (size_t)b * NC;
    const int* ynr = yn + (size_t)b * NC;
    for (int i = tid; i < ne; i += BDIM) {
        int c = d_cls[i];
        int l = (int)d_grp[i];
        atomicMax(&s_gmax[l], fenc(__ldg(xr + c)));
        if (__ldg(yr  + c)) atomicOr(&s_act[l], 1);
        if (__ldg(ynr + c)) atomicOr(&s_an[l],  1);
    }
    __syncthreads();

    if (tid == 0) {
        float gs[NL];
        float umax = 0.0f;
#pragma unroll
        for (int l = 0; l < NL; ++l) {
            gs[l] = sigmoidf_(fdec(s_gmax[l]));
            umax  = fmaxf(umax, gs[l]);
        }
        int g = -1;
#pragma unroll
        for (int l = 0; l < NL; ++l)
            if (g < 0 && s_act[l]) g = l;

        float imax = 0.0f, ineg = 0.0f;
#pragma unroll
        for (int l = 0; l < NL; ++l) {
            if (l != g)  imax = fmaxf(imax, gs[l]);
            if (s_an[l]) ineg = fmaxf(ineg, gs[l]);
        }

        float loss;
        if (g < 0) {
            loss = 0.5f * rankl(thres, umax) + 0.5f * rankl(thres, ineg);
        } else {
            loss = rankl(gs[g], thres);
            if (imax > 0.0f) loss += 0.5f * rankl(thres, imax);
            loss += 0.5f * ((ineg > 0.0f) ? rankl(thres, ineg)
                                          : rankl(thres, imax));
        }
        d_loss[b] = loss;
    }
}

// Deterministic fixed-order reduction of the per-row losses.
__global__ void __launch_bounds__(256)
reduce_kernel(float* __restrict__ out) {
    __shared__ float sh[256];
    int tid = threadIdx.x;
    float s = 0.0f;
#pragma unroll
    for (int k = 0; k < NB / 256; ++k)
        s += d_loss[tid + k * 256];
    sh[tid] = s;
    __syncthreads();
    for (int o = 128; o > 0; o >>= 1) {
        if (tid < o) sh[tid] += sh[tid + o];
        __syncthreads();
    }
    if (tid == 0) out[0] = sh[0];
}

extern "C" void kernel_launch(void* const* d_in, const int* in_sizes, int n_in,
                              void* d_out, int out_size) {
    const float* x    = (const float*)d_in[0];
    const int*   y    = (const int*)d_in[1];
    const int*   yn   = (const int*)d_in[2];
    const void*  mask = (const void*)d_in[3];
    float*       out  = (float*)d_out;

    zero_kernel<<<1, 32>>>();
    detect_kernel<<<64, 256>>>((const unsigned char*)mask);
    decide_kernel<<<1, 32>>>();
    build_kernel<<<192, 256>>>(mask);
    loss_kernel<<<NB, BDIM>>>(x, y, yn);
    reduce_kernel<<<1, 256>>>(out);
}

// round 4
// speedup vs baseline: 1.7690x; 1.2340x over previous
#include <cuda_runtime.h>
#include <math.h>
#include <stdint.h>

#define NB   2048
#define NC   9605
#define NL   20
#define MAXE 4096
#define BDIM 256
#define CAP  2048
#define T1   2.5f          // ~60 candidates expected for N(0,1)
#define T2   1.0f          // ~1500 candidates expected

// Scratch (no allocations allowed)
__device__ int   d_ent[MAXE];     // (grp<<16) | cls
__device__ int   d_cnt;
__device__ float d_loss[NB];
__device__ int   d_done;

// ---------------------------------------------------------------------------
// Single-block setup: detect mask dtype (bool widened to int32/float32 or raw
// uint8) by byte-position histogram, then compact group_mask into entry list.
// ---------------------------------------------------------------------------
__global__ void __launch_bounds__(1024)
setup_kernel(const void* __restrict__ maskv) {
    __shared__ int h[4];
    const int tid = threadIdx.x;
    if (tid < 4) h[tid] = 0;
    if (tid == 0) { d_cnt = 0; d_done = 0; }
    __syncthreads();

    const int total = NL * NC;
    // --- detect: flag nonzero bytes by (offset mod 4) over first `total` bytes
    {
        const uint4* r4 = (const uint4*)maskv;
        const unsigned char* r8 = (const unsigned char*)maskv;
        int f0 = 0, f1 = 0, f2 = 0, f3 = 0;
        int nv = total >> 4;
        for (int i = tid; i < nv; i += 1024) {
            uint4 w = __ldg(r4 + i);
            unsigned a = w.x | w.y | w.z | w.w;
            f0 |= (a & 0x000000FFu) != 0;
            f1 |= (a & 0x0000FF00u) != 0;
            f2 |= (a & 0x00FF0000u) != 0;
            f3 |= (a & 0xFF000000u) != 0;
        }
        for (int i = (nv << 4) + tid; i < total; i += 1024)
            if (r8[i]) { int m = i & 3;
                f0 |= (m == 0); f1 |= (m == 1); f2 |= (m == 2); f3 |= (m == 3); }
        if (f0) atomicOr(&h[0], 1);
        if (f1) atomicOr(&h[1], 1);
        if (f2) atomicOr(&h[2], 1);
        if (f3) atomicOr(&h[3], 1);
    }
    __syncthreads();
    int mode;  // 0 = uint8, 1 = int32, 2 = float32
    {
        int h0 = h[0], h1 = h[1], h2 = h[2], h3 = h[3];
        if (h0 && !h1 && !h2 && !h3)        mode = 1;
        else if (!h0 && !h1 && (h2 || h3))  mode = 2;
        else                                 mode = 0;
    }

    // --- build entry list
    if (mode != 0) {
        const int4*   m4 = (const int4*)maskv;   // int32 and float32 both: !=0 test on bits
        int nv = total >> 2;
        for (int i = tid; i < nv; i += 1024) {
            int4 w = __ldg(m4 + i);
            int base = i << 2;
#pragma unroll
            for (int u = 0; u < 4; ++u) {
                int bits = (u == 0) ? w.x : (u == 1) ? w.y : (u == 2) ? w.z : w.w;
                if (bits != 0) {
                    int idx = base + u;
                    int p = atomicAdd(&d_cnt, 1);
                    if (p < MAXE) d_ent[p] = ((idx / NC) << 16) | (idx % NC);
                }
            }
        }
        for (int idx = (nv << 2) + tid; idx < total; idx += 1024) {
            if (((const int*)maskv)[idx] != 0) {
                int p = atomicAdd(&d_cnt, 1);
                if (p < MAXE) d_ent[p] = ((idx / NC) << 16) | (idx % NC);
            }
        }
    } else {
        const unsigned char* m8 = (const unsigned char*)maskv;
        for (int idx = tid; idx < total; idx += 1024) {
            if (m8[idx]) {
                int p = atomicAdd(&d_cnt, 1);
                if (p < MAXE) d_ent[p] = ((idx / NC) << 16) | (idx % NC);
            }
        }
    }
}

__device__ __forceinline__ float sigmoidf_(float v) {
    return 1.0f / (1.0f + expf(-v));
}
__device__ __forceinline__ float rankl(float x1, float x2) {
    float d = x2 - x1 + 0.05f;
    float s = 1.0f / (1.0f + expf(-10.0f * d));
    return (d > 0.0f) ? 2.0f * s : s;
}
__device__ __forceinline__ unsigned fenc(float v) {
    unsigned u = __float_as_uint(v);
    return (u & 0x80000000u) ? ~u : (u | 0x80000000u);
}
__device__ __forceinline__ float fdec(unsigned u) {
    return (u & 0x80000000u) ? __uint_as_float(u ^ 0x80000000u)
                             : __uint_as_float(~u);
}

// ---------------------------------------------------------------------------
// Per-row loss: float4 scan for top-11 threshold candidates, packed-entry
// gather for group max / activity, scalar loss, last-block final reduction.
// ---------------------------------------------------------------------------
__global__ void __launch_bounds__(BDIM)
loss_kernel(const float* __restrict__ x,
            const int*   __restrict__ y,
            const int*   __restrict__ yn,
            float*       __restrict__ out) {
    const int b   = blockIdx.x;
    const int tid = threadIdx.x;
    const float* xr = x + (size_t)b * NC;

    __shared__ float    s_cand[CAP];
    __shared__ int      s_cnt;
    __shared__ float    s_v11;
    __shared__ unsigned s_gmax[NL];
    __shared__ int      s_act[NL];
    __shared__ int      s_an[NL];
    __shared__ int      s_last;

    if (tid < NL) { s_gmax[tid] = 0u; s_act[tid] = 0; s_an[tid] = 0; }

    // vector-body geometry (rows start at 4*b mod 16 bytes)
    const int head = (int)((16u - ((unsigned)(uintptr_t)xr & 15u)) & 15u) >> 2;
    const float4* xv = (const float4*)(xr + head);
    const int nvec = (NC - head) >> 2;
    const int tail0 = head + (nvec << 2);

    // one scan pass; store=true collects candidates > thr, else counts only
    auto scan = [&](float thr, bool store) -> int {
        if (tid == 0) s_cnt = 0;
        __syncthreads();
        int local = 0;
        auto emit = [&](float v) {
            if (v > thr) {
                if (store) { int p = atomicAdd(&s_cnt, 1); if (p < CAP) s_cand[p] = v; }
                else local++;
            }
        };
        if (tid < head) emit(__ldg(xr + tid));
        for (int i = tid; i < nvec; i += BDIM) {
            float4 v = __ldg(xv + i);
            emit(v.x); emit(v.y); emit(v.z); emit(v.w);
        }
        for (int c = tail0 + tid; c < NC; c += BDIM) emit(__ldg(xr + c));
        if (!store && local) atomicAdd(&s_cnt, local);
        __syncthreads();
        return s_cnt;
    };

    float thr = T1;
    int cnt = scan(thr, true);
    if (cnt < 11 || cnt > CAP) {
        thr = T2;
        cnt = scan(thr, true);
        if (cnt < 11 || cnt > CAP) {
            // bisection fallback (unreachable for the bench distribution)
            float tlo, thi;
            if (cnt < 11) { thi = thr; tlo = -3.0e38f; }
            else          { tlo = thr; thi = 3.0e38f; }
            for (int it = 0; it < 120; ++it) {
                float mid = 0.5f * (tlo + thi);
                int c2 = scan(mid, false);
                if (c2 > CAP)      tlo = mid;
                else if (c2 < 11)  thi = mid;
                else { thr = mid; break; }
                thr = mid;
            }
            cnt = scan(thr, true);
            if (cnt > CAP) cnt = CAP;  // safety clamp
        }
    }

    // exact 11th largest among candidates (all non-candidates are <= thr)
    for (int i = tid; i < cnt; i += BDIM) {
        float vi = s_cand[i];
        int rank = 0;
        for (int j = 0; j < cnt; ++j) {
            float vj = s_cand[j];
            rank += (vj > vi) || (vj == vi && j < i);
        }
        if (rank == 10) s_v11 = vi;
    }
    __syncthreads();
    const float thres = fmaxf(sigmoidf_(s_v11), 0.5f);

    // ---- gather: 4-entry batches, loads hoisted ahead of atomics
    int ne = d_cnt; if (ne > MAXE) ne = MAXE;
    const int* yr  = y  + (size_t)b * NC;
    const int* ynr = yn + (size_t)b * NC;
    for (int base = 0; base < ne; base += 4 * BDIM) {
        int   ent[4]; bool val[4];
        float xvv[4]; int yv[4], ynv[4];
#pragma unroll
        for (int u = 0; u < 4; ++u) {
            int i = base + u * BDIM + tid;
            val[u] = (i < ne);
            ent[u] = val[u] ? __ldg(&d_ent[i]) : 0;
        }
#pragma unroll
        for (int u = 0; u < 4; ++u) {
            if (val[u]) {
                int c = ent[u] & 0xFFFF;
                xvv[u] = __ldg(xr + c);
                yv[u]  = __ldg(yr + c);
                ynv[u] = __ldg(ynr + c);
            }
        }
#pragma unroll
        for (int u = 0; u < 4; ++u) {
            if (val[u]) {
                int l = ent[u] >> 16;
                atomicMax(&s_gmax[l], fenc(xvv[u]));
                if (yv[u])  atomicOr(&s_act[l], 1);
                if (ynv[u]) atomicOr(&s_an[l],  1);
            }
        }
    }
    __syncthreads();

    if (tid == 0) {
        float gs[NL];
        float umax = 0.0f;
#pragma unroll
        for (int l = 0; l < NL; ++l) {
            gs[l] = sigmoidf_(fdec(s_gmax[l]));
            umax  = fmaxf(umax, gs[l]);
        }
        int g = -1;
#pragma unroll
        for (int l = 0; l < NL; ++l)
            if (g < 0 && s_act[l]) g = l;

        float imax = 0.0f, ineg = 0.0f;
#pragma unroll
        for (int l = 0; l < NL; ++l) {
            if (l != g)  imax = fmaxf(imax, gs[l]);
            if (s_an[l]) ineg = fmaxf(ineg, gs[l]);
        }

        float loss;
        if (g < 0) {
            loss = 0.5f * rankl(thres, umax) + 0.5f * rankl(thres, ineg);
        } else {
            loss = rankl(gs[g], thres);
            if (imax > 0.0f) loss += 0.5f * rankl(thres, imax);
            loss += 0.5f * ((ineg > 0.0f) ? rankl(thres, ineg)
                                          : rankl(thres, imax));
        }
        d_loss[b] = loss;
        __threadfence();
        int done = atomicAdd(&d_done, 1);
        s_last = (done == NB - 1);
    }
    __syncthreads();

    // last finished block performs the deterministic fixed-order reduction
    if (s_last) {
        __shared__ float sh[BDIM];
        float s = 0.0f;
#pragma unroll
        for (int k = 0; k < NB / BDIM; ++k)
            s += d_loss[tid + k * BDIM];
        sh[tid] = s;
        __syncthreads();
        for (int o = BDIM / 2; o > 0; o >>= 1) {
            if (tid < o) sh[tid] += sh[tid + o];
            __syncthreads();
        }
        if (tid == 0) out[0] = sh[0];
    }
}

extern "C" void kernel_launch(void* const* d_in, const int* in_sizes, int n_in,
                              void* d_out, int out_size) {
    const float* x    = (const float*)d_in[0];
    const int*   y    = (const int*)d_in[1];
    const int*   yn   = (const int*)d_in[2];
    const void*  mask = (const void*)d_in[3];
    float*       out  = (float*)d_out;

    setup_kernel<<<1, 1024>>>(mask);
    loss_kernel<<<NB, BDIM>>>(x, y, yn, out);
}

// round 5
// speedup vs baseline: 2.7201x; 1.5376x over previous
#include <cuda_runtime.h>
#include <math.h>
#include <stdint.h>

#define NB   2048
#define NC   9605
#define NL   20
#define MAXE 4096
#define BDIM 256
#define CAP  2048
#define T1   2.5f          // ~60 candidates expected for N(0,1)
#define T2   1.0f          // ~1500 candidates expected

// Scratch (no allocations allowed)
__device__ int   d_ent[MAXE];     // (grp<<16) | cls
__device__ int   d_cnt;
__device__ int   d_hist[4];
__device__ float d_loss[NB];
__device__ int   d_done;

__global__ void init_kernel() {
    if (threadIdx.x == 0) {
        d_cnt = 0; d_done = 0;
        d_hist[0] = d_hist[1] = d_hist[2] = d_hist[3] = 0;
    }
}

// Flag nonzero bytes by (offset mod 4) over the first NL*NC BYTES (safe lower
// bound under every candidate dtype width) to infer the mask dtype.
__global__ void __launch_bounds__(256)
detect_kernel(const unsigned char* __restrict__ raw) {
    const int total = NL * NC;
    const uint4* r4 = (const uint4*)raw;
    int f0 = 0, f1 = 0, f2 = 0, f3 = 0;
    int nv = total >> 4;
    for (int i = blockIdx.x * blockDim.x + threadIdx.x; i < nv;
         i += gridDim.x * blockDim.x) {
        uint4 w = __ldg(r4 + i);
        unsigned a = w.x | w.y | w.z | w.w;
        f0 |= (a & 0x000000FFu) != 0;
        f1 |= (a & 0x0000FF00u) != 0;
        f2 |= (a & 0x00FF0000u) != 0;
        f3 |= (a & 0xFF000000u) != 0;
    }
    if (blockIdx.x == 0) {
        for (int i = (nv << 4) + threadIdx.x; i < total; i += blockDim.x)
            if (raw[i]) { int m = i & 3;
                f0 |= (m == 0); f1 |= (m == 1); f2 |= (m == 2); f3 |= (m == 3); }
    }
    if (f0) atomicOr(&d_hist[0], 1);
    if (f1) atomicOr(&d_hist[1], 1);
    if (f2) atomicOr(&d_hist[2], 1);
    if (f3) atomicOr(&d_hist[3], 1);
}

// Compact group_mask [L, C] into a packed (grp<<16)|cls entry list.
__global__ void __launch_bounds__(256)
build_kernel(const void* __restrict__ maskv) {
    int h0 = d_hist[0], h1 = d_hist[1], h2 = d_hist[2], h3 = d_hist[3];
    int mode;  // 0 = uint8, 1 = int32, 2 = float32
    if (h0 && !h1 && !h2 && !h3)        mode = 1;
    else if (!h0 && !h1 && (h2 || h3))  mode = 2;
    else                                 mode = 0;

    const int total = NL * NC;
    const int gs = gridDim.x * blockDim.x;
    const int t0 = blockIdx.x * blockDim.x + threadIdx.x;

    if (mode != 0) {
        const int4* m4 = (const int4*)maskv;  // int32/float32: !=0 bit test
        int nv = total >> 2;
        for (int i = t0; i < nv; i += gs) {
            int4 w = __ldg(m4 + i);
            int base = i << 2;
#pragma unroll
            for (int u = 0; u < 4; ++u) {
                int bits = (u == 0) ? w.x : (u == 1) ? w.y : (u == 2) ? w.z : w.w;
                if (bits != 0) {
                    int idx = base + u;
                    int p = atomicAdd(&d_cnt, 1);
                    if (p < MAXE) d_ent[p] = ((idx / NC) << 16) | (idx % NC);
                }
            }
        }
        for (int idx = (nv << 2) + t0; idx < total; idx += gs) {
            if (((const int*)maskv)[idx] != 0) {
                int p = atomicAdd(&d_cnt, 1);
                if (p < MAXE) d_ent[p] = ((idx / NC) << 16) | (idx % NC);
            }
        }
    } else {
        const unsigned char* m8 = (const unsigned char*)maskv;
        for (int idx = t0; idx < total; idx += gs) {
            if (m8[idx]) {
                int p = atomicAdd(&d_cnt, 1);
                if (p < MAXE) d_ent[p] = ((idx / NC) << 16) | (idx % NC);
            }
        }
    }
}

__device__ __forceinline__ float sigmoidf_(float v) {
    return 1.0f / (1.0f + expf(-v));
}
__device__ __forceinline__ float rankl(float x1, float x2) {
    float d = x2 - x1 + 0.05f;
    float s = 1.0f / (1.0f + expf(-10.0f * d));
    return (d > 0.0f) ? 2.0f * s : s;
}
__device__ __forceinline__ unsigned fenc(float v) {
    unsigned u = __float_as_uint(v);
    return (u & 0x80000000u) ? ~u : (u | 0x80000000u);
}
__device__ __forceinline__ float fdec(unsigned u) {
    return (u & 0x80000000u) ? __uint_as_float(u ^ 0x80000000u)
                             : __uint_as_float(~u);
}

// ---------------------------------------------------------------------------
// Per-row loss: float4 scan for top-11 threshold candidates, packed-entry
// gather for group max / activity, scalar loss, last-block final reduction.
// ---------------------------------------------------------------------------
__global__ void __launch_bounds__(BDIM, 8)
loss_kernel(const float* __restrict__ x,
            const int*   __restrict__ y,
            const int*   __restrict__ yn,
            float*       __restrict__ out) {
    const int b   = blockIdx.x;
    const int tid = threadIdx.x;
    const float* xr = x + (size_t)b * NC;

    __shared__ float    s_cand[CAP];
    __shared__ int      s_cnt;
    __shared__ float    s_v11;
    __shared__ unsigned s_gmax[NL];
    __shared__ int      s_act[NL];
    __shared__ int      s_an[NL];
    __shared__ int      s_last;

    if (tid < NL) { s_gmax[tid] = 0u; s_act[tid] = 0; s_an[tid] = 0; }

    // vector-body geometry (rows start at 4*b mod 16 bytes)
    const int head = (int)((16u - ((unsigned)(uintptr_t)xr & 15u)) & 15u) >> 2;
    const float4* xv = (const float4*)(xr + head);
    const int nvec = (NC - head) >> 2;
    const int tail0 = head + (nvec << 2);

    // one scan pass; store=true collects candidates > thr, else counts only
    auto scan = [&](float thr, bool store) -> int {
        if (tid == 0) s_cnt = 0;
        __syncthreads();
        int local = 0;
        auto emit = [&](float v) {
            if (v > thr) {
                if (store) { int p = atomicAdd(&s_cnt, 1); if (p < CAP) s_cand[p] = v; }
                else local++;
            }
        };
        if (tid < head) emit(__ldg(xr + tid));
        int i = tid;
        for (; i + BDIM < nvec; i += 2 * BDIM) {
            float4 v0 = __ldg(xv + i);
            float4 v1 = __ldg(xv + i + BDIM);
            emit(v0.x); emit(v0.y); emit(v0.z); emit(v0.w);
            emit(v1.x); emit(v1.y); emit(v1.z); emit(v1.w);
        }
        for (; i < nvec; i += BDIM) {
            float4 v = __ldg(xv + i);
            emit(v.x); emit(v.y); emit(v.z); emit(v.w);
        }
        for (int c = tail0 + tid; c < NC; c += BDIM) emit(__ldg(xr + c));
        if (!store && local) atomicAdd(&s_cnt, local);
        __syncthreads();
        return s_cnt;
    };

    float thr = T1;
    int cnt = scan(thr, true);
    if (cnt < 11 || cnt > CAP) {
        thr = T2;
        cnt = scan(thr, true);
        if (cnt < 11 || cnt > CAP) {
            // bisection fallback (unreachable for the bench distribution)
            float tlo, thi;
            if (cnt < 11) { thi = thr; tlo = -3.0e38f; }
            else          { tlo = thr; thi = 3.0e38f; }
            for (int it = 0; it < 120; ++it) {
                float mid = 0.5f * (tlo + thi);
                int c2 = scan(mid, false);
                if (c2 > CAP)      tlo = mid;
                else if (c2 < 11)  thi = mid;
                else { thr = mid; break; }
                thr = mid;
            }
            cnt = scan(thr, true);
            if (cnt > CAP) cnt = CAP;  // safety clamp
        }
    }

    // exact 11th largest among candidates (all non-candidates are <= thr)
    for (int i = tid; i < cnt; i += BDIM) {
        float vi = s_cand[i];
        int rank = 0;
        for (int j = 0; j < cnt; ++j) {
            float vj = s_cand[j];
            rank += (vj > vi) || (vj == vi && j < i);
        }
        if (rank == 10) s_v11 = vi;
    }
    __syncthreads();
    const float thres = fmaxf(sigmoidf_(s_v11), 0.5f);

    // ---- gather: 4-entry batches, loads hoisted ahead of atomics
    int ne = d_cnt; if (ne > MAXE) ne = MAXE;
    const int* yr  = y  + (size_t)b * NC;
    const int* ynr = yn + (size_t)b * NC;
    for (int base = 0; base < ne; base += 4 * BDIM) {
        int   ent[4]; bool val[4];
        float xvv[4]; int yv[4], ynv[4];
#pragma unroll
        for (int u = 0; u < 4; ++u) {
            int i = base + u * BDIM + tid;
            val[u] = (i < ne);
            ent[u] = val[u] ? __ldg(&d_ent[i]) : 0;
        }
#pragma unroll
        for (int u = 0; u < 4; ++u) {
            if (val[u]) {
                int c = ent[u] & 0xFFFF;
                xvv[u] = __ldg(xr + c);
                yv[u]  = __ldg(yr + c);
                ynv[u] = __ldg(ynr + c);
            }
        }
#pragma unroll
        for (int u = 0; u < 4; ++u) {
            if (val[u]) {
                int l = ent[u] >> 16;
                atomicMax(&s_gmax[l], fenc(xvv[u]));
                if (yv[u])  atomicOr(&s_act[l], 1);
                if (ynv[u]) atomicOr(&s_an[l],  1);
            }
        }
    }
    __syncthreads();

    if (tid == 0) {
        float gs[NL];
        float umax = 0.0f;
#pragma unroll
        for (int l = 0; l < NL; ++l) {
            gs[l] = sigmoidf_(fdec(s_gmax[l]));
            umax  = fmaxf(umax, gs[l]);
        }
        int g = -1;
#pragma unroll
        for (int l = 0; l < NL; ++l)
            if (g < 0 && s_act[l]) g = l;

        float imax = 0.0f, ineg = 0.0f;
#pragma unroll
        for (int l = 0; l < NL; ++l) {
            if (l != g)  imax = fmaxf(imax, gs[l]);
            if (s_an[l]) ineg = fmaxf(ineg, gs[l]);
        }

        float loss;
        if (g < 0) {
            loss = 0.5f * rankl(thres, umax) + 0.5f * rankl(thres, ineg);
        } else {
            loss = rankl(gs[g], thres);
            if (imax > 0.0f) loss += 0.5f * rankl(thres, imax);
            loss += 0.5f * ((ineg > 0.0f) ? rankl(thres, ineg)
                                          : rankl(thres, imax));
        }
        d_loss[b] = loss;
        __threadfence();
        int done = atomicAdd(&d_done, 1);
        s_last = (done == NB - 1);
    }
    __syncthreads();

    // last finished block performs the deterministic fixed-order reduction
    if (s_last) {
        __shared__ float sh[BDIM];
        float s = 0.0f;
#pragma unroll
        for (int k = 0; k < NB / BDIM; ++k)
            s += d_loss[tid + k * BDIM];
        sh[tid] = s;
        __syncthreads();
        for (int o = BDIM / 2; o > 0; o >>= 1) {
            if (tid < o) sh[tid] += sh[tid + o];
            __syncthreads();
        }
        if (tid == 0) out[0] = sh[0];
    }
}

extern "C" void kernel_launch(void* const* d_in, const int* in_sizes, int n_in,
                              void* d_out, int out_size) {
    const float* x    = (const float*)d_in[0];
    const int*   y    = (const int*)d_in[1];
    const int*   yn   = (const int*)d_in[2];
    const void*  mask = (const void*)d_in[3];
    float*       out  = (float*)d_out;

    init_kernel<<<1, 32>>>();
    detect_kernel<<<64, 256>>>((const unsigned char*)mask);
    build_kernel<<<148, 256>>>(mask);
    loss_kernel<<<NB, BDIM>>>(x, y, yn, out);
}

// round 6
// speedup vs baseline: 2.8279x; 1.0396x over previous
#include <cuda_runtime.h>
#include <math.h>
#include <stdint.h>

#define NB   2048
#define NC   9605
#define NL   20
#define BDIM 256
#define CAP  2048
#define T1   2.5f          // ~60 candidates expected for N(0,1)
#define T2   1.0f          // ~1500 candidates expected

// Scratch (no allocations allowed)
__device__ unsigned char d_tab[NC];   // class -> group (0xFF = not whitelisted)
__device__ int   d_hist[4];
__device__ float d_loss[NB];
__device__ int   d_done;

__global__ void __launch_bounds__(256)
init_kernel() {
    int t0 = blockIdx.x * blockDim.x + threadIdx.x;
    if (t0 == 0) {
        d_done = 0;
        d_hist[0] = d_hist[1] = d_hist[2] = d_hist[3] = 0;
    }
    for (int i = t0; i < NC; i += gridDim.x * blockDim.x)
        d_tab[i] = 0xFF;
}

// Flag nonzero bytes by (offset mod 4) over the first NL*NC BYTES (safe lower
// bound under every candidate dtype width) to infer the mask dtype.
__global__ void __launch_bounds__(256)
detect_kernel(const unsigned char* __restrict__ raw) {
    const int total = NL * NC;
    const uint4* r4 = (const uint4*)raw;
    int f0 = 0, f1 = 0, f2 = 0, f3 = 0;
    int nv = total >> 4;
    for (int i = blockIdx.x * blockDim.x + threadIdx.x; i < nv;
         i += gridDim.x * blockDim.x) {
        uint4 w = __ldg(r4 + i);
        unsigned a = w.x | w.y | w.z | w.w;
        f0 |= (a & 0x000000FFu) != 0;
        f1 |= (a & 0x0000FF00u) != 0;
        f2 |= (a & 0x00FF0000u) != 0;
        f3 |= (a & 0xFF000000u) != 0;
    }
    if (blockIdx.x == 0) {
        for (int i = (nv << 4) + threadIdx.x; i < total; i += blockDim.x)
            if (raw[i]) { int m = i & 3;
                f0 |= (m == 0); f1 |= (m == 1); f2 |= (m == 2); f3 |= (m == 3); }
    }
    if (f0) atomicOr(&d_hist[0], 1);
    if (f1) atomicOr(&d_hist[1], 1);
    if (f2) atomicOr(&d_hist[2], 1);
    if (f3) atomicOr(&d_hist[3], 1);
}

// Fill class -> group table from group_mask [L, C], honoring detected dtype.
__global__ void __launch_bounds__(256)
build_kernel(const void* __restrict__ maskv) {
    int h0 = d_hist[0], h1 = d_hist[1], h2 = d_hist[2], h3 = d_hist[3];
    int mode;  // 0 = uint8, 1 = int32, 2 = float32
    if (h0 && !h1 && !h2 && !h3)        mode = 1;
    else if (!h0 && !h1 && (h2 || h3))  mode = 2;
    else                                 mode = 0;

    const int total = NL * NC;
    const int gs = gridDim.x * blockDim.x;
    const int t0 = blockIdx.x * blockDim.x + threadIdx.x;

    if (mode != 0) {
        const int4* m4 = (const int4*)maskv;  // int32/float32: !=0 bit test
        int nv = total >> 2;
        for (int i = t0; i < nv; i += gs) {
            int4 w = __ldg(m4 + i);
            int base = i << 2;
#pragma unroll
            for (int u = 0; u < 4; ++u) {
                int bits = (u == 0) ? w.x : (u == 1) ? w.y : (u == 2) ? w.z : w.w;
                if (bits != 0) {
                    int idx = base + u;
                    d_tab[idx % NC] = (unsigned char)(idx / NC);
                }
            }
        }
        for (int idx = (nv << 2) + t0; idx < total; idx += gs)
            if (((const int*)maskv)[idx] != 0)
                d_tab[idx % NC] = (unsigned char)(idx / NC);
    } else {
        const unsigned char* m8 = (const unsigned char*)maskv;
        for (int idx = t0; idx < total; idx += gs)
            if (m8[idx])
                d_tab[idx % NC] = (unsigned char)(idx / NC);
    }
}

__device__ __forceinline__ float sigmoidf_(float v) {
    return 1.0f / (1.0f + expf(-v));
}
__device__ __forceinline__ float rankl(float x1, float x2) {
    float d = x2 - x1 + 0.05f;
    float s = 1.0f / (1.0f + expf(-10.0f * d));
    return (d > 0.0f) ? 2.0f * s : s;
}
__device__ __forceinline__ unsigned fenc(float v) {
    unsigned u = __float_as_uint(v);
    return (u & 0x80000000u) ? ~u : (u | 0x80000000u);
}
__device__ __forceinline__ float fdec(unsigned u) {
    return (u & 0x80000000u) ? __uint_as_float(u ^ 0x80000000u)
                             : __uint_as_float(~u);
}

// ---------------------------------------------------------------------------
// Fully fused per-row pass: one streaming scan of x collects top-11 threshold
// candidates AND (via the class->group table) per-group max + y/y_neg activity,
// loading y/yn chunks only where a whitelist class is present.
// ---------------------------------------------------------------------------
__global__ void __launch_bounds__(BDIM, 8)
loss_kernel(const float* __restrict__ x,
            const int*   __restrict__ y,
            const int*   __restrict__ yn,
            float*       __restrict__ out) {
    const int b   = blockIdx.x;
    const int tid = threadIdx.x;
    const float* xr  = x  + (size_t)b * NC;
    const int*   yr  = y  + (size_t)b * NC;
    const int*   ynr = yn + (size_t)b * NC;

    __shared__ unsigned char s_tab[NC + 3]; // table shifted by `head`
    __shared__ float    s_cand[CAP];
    __shared__ int      s_cnt;
    __shared__ float    s_v11;
    __shared__ unsigned s_gmax[NL];
    __shared__ int      s_act[NL];
    __shared__ int      s_an[NL];
    __shared__ int      s_last;

    if (tid == 0) s_cnt = 0;
    if (tid < NL) { s_gmax[tid] = 0u; s_act[tid] = 0; s_an[tid] = 0; }

    // vector-body geometry (all three rows share the same misalignment)
    const int head = (int)((16u - ((unsigned)(uintptr_t)xr & 15u)) & 15u) >> 2;
    const float4* xv  = (const float4*)(xr  + head);
    const int4*   yv4 = (const int4*)(yr  + head);
    const int4*   ynv4= (const int4*)(ynr + head);
    const int nvec  = (NC - head) >> 2;
    const int tail0 = head + (nvec << 2);

    // stage shifted table: s_tab[j] = d_tab[head + j]
    for (int j = tid; j < NC - head; j += BDIM) s_tab[j] = d_tab[head + j];
    __syncthreads();

    auto wl_update = [&](int l, float v, int yi, int yni) {
        atomicMax(&s_gmax[l], fenc(v));
        if (yi)  atomicOr(&s_act[l], 1);
        if (yni) atomicOr(&s_an[l],  1);
    };

    // ---- fused pass: candidates > T1, plus whitelist group stats
    {
        int local_over = 0;  // unused here; candidates go straight to smem
        (void)local_over;
        // head scalars
        if (tid < head) {
            float v = __ldg(xr + tid);
            if (v > T1) { int p = atomicAdd(&s_cnt, 1); if (p < CAP) s_cand[p] = v; }
            int t = d_tab[tid];
            if (t != 0xFF)
                wl_update(t, v, __ldg(yr + tid), __ldg(ynr + tid));
        }
        for (int i = tid; i < nvec; i += BDIM) {
            float4 v = __ldcs(xv + i);
            unsigned tw = *(const unsigned*)(s_tab + (i << 2)); // 4-aligned
            if (v.x > T1) { int p = atomicAdd(&s_cnt, 1); if (p < CAP) s_cand[p] = v.x; }
            if (v.y > T1) { int p = atomicAdd(&s_cnt, 1); if (p < CAP) s_cand[p] = v.y; }
            if (v.z > T1) { int p = atomicAdd(&s_cnt, 1); if (p < CAP) s_cand[p] = v.z; }
            if (v.w > T1) { int p = atomicAdd(&s_cnt, 1); if (p < CAP) s_cand[p] = v.w; }
            if (tw != 0xFFFFFFFFu) {
                int4 yq  = __ldcs(yv4 + i);
                int4 ynq = __ldcs(ynv4 + i);
                unsigned t0 =  tw        & 0xFF;
                unsigned t1 = (tw >> 8)  & 0xFF;
                unsigned t2 = (tw >> 16) & 0xFF;
                unsigned t3 = (tw >> 24) & 0xFF;
                if (t0 != 0xFF) wl_update((int)t0, v.x, yq.x, ynq.x);
                if (t1 != 0xFF) wl_update((int)t1, v.y, yq.y, ynq.y);
                if (t2 != 0xFF) wl_update((int)t2, v.z, yq.z, ynq.z);
                if (t3 != 0xFF) wl_update((int)t3, v.w, yq.w, ynq.w);
            }
        }
        for (int c = tail0 + tid; c < NC; c += BDIM) {
            float v = __ldg(xr + c);
            if (v > T1) { int p = atomicAdd(&s_cnt, 1); if (p < CAP) s_cand[p] = v; }
            int t = s_tab[c - head];
            if (t != 0xFF)
                wl_update(t, v, __ldg(yr + c), __ldg(ynr + c));
        }
    }
    __syncthreads();
    int cnt = s_cnt;

    // x-only rescan helper for fallback tiers (row is cache-hot)
    auto rescan = [&](float thr, bool store) -> int {
        if (tid == 0) s_cnt = 0;
        __syncthreads();
        int local = 0;
        auto emit = [&](float v) {
            if (v > thr) {
                if (store) { int p = atomicAdd(&s_cnt, 1); if (p < CAP) s_cand[p] = v; }
                else local++;
            }
        };
        if (tid < head) emit(__ldg(xr + tid));
        for (int i = tid; i < nvec; i += BDIM) {
            float4 v = __ldg(xv + i);
            emit(v.x); emit(v.y); emit(v.z); emit(v.w);
        }
        for (int c = tail0 + tid; c < NC; c += BDIM) emit(__ldg(xr + c));
        if (!store && local) atomicAdd(&s_cnt, local);
        __syncthreads();
        return s_cnt;
    };

    if (cnt < 11 || cnt > CAP) {
        float thr = T2;
        cnt = rescan(thr, true);
        if (cnt < 11 || cnt > CAP) {
            // bisection fallback (unreachable for the bench distribution)
            float tlo, thi;
            if (cnt < 11) { thi = thr; tlo = -3.0e38f; }
            else          { tlo = thr; thi = 3.0e38f; }
            for (int it = 0; it < 120; ++it) {
                float mid = 0.5f * (tlo + thi);
                int c2 = rescan(mid, false);
                if (c2 > CAP)      tlo = mid;
                else if (c2 < 11)  thi = mid;
                else { thr = mid; break; }
                thr = mid;
            }
            cnt = rescan(thr, true);
            if (cnt > CAP) cnt = CAP;
        }
    }

    // exact 11th largest among candidates (all non-candidates are <= threshold)
    for (int i = tid; i < cnt; i += BDIM) {
        float vi = s_cand[i];
        int rank = 0;
        for (int j = 0; j < cnt; ++j) {
            float vj = s_cand[j];
            rank += (vj > vi) || (vj == vi && j < i);
        }
        if (rank == 10) s_v11 = vi;
    }
    __syncthreads();
    const float thres = fmaxf(sigmoidf_(s_v11), 0.5f);

    if (tid == 0) {
        float gs[NL];
        float umax = 0.0f;
#pragma unroll
        for (int l = 0; l < NL; ++l) {
            gs[l] = sigmoidf_(fdec(s_gmax[l]));
            umax  = fmaxf(umax, gs[l]);
        }
        int g = -1;
#pragma unroll
        for (int l = 0; l < NL; ++l)
            if (g < 0 && s_act[l]) g = l;

        float imax = 0.0f, ineg = 0.0f;
#pragma unroll
        for (int l = 0; l < NL; ++l) {
            if (l != g)  imax = fmaxf(imax, gs[l]);
            if (s_an[l]) ineg = fmaxf(ineg, gs[l]);
        }

        float loss;
        if (g < 0) {
            loss = 0.5f * rankl(thres, umax) + 0.5f * rankl(thres, ineg);
        } else {
            loss = rankl(gs[g], thres);
            if (imax > 0.0f) loss += 0.5f * rankl(thres, imax);
            loss += 0.5f * ((ineg > 0.0f) ? rankl(thres, ineg)
                                          : rankl(thres, imax));
        }
        d_loss[b] = loss;
        __threadfence();
        int done = atomicAdd(&d_done, 1);
        s_last = (done == NB - 1);
    }
    __syncthreads();

    // last finished block performs the deterministic fixed-order reduction
    if (s_last) {
        __shared__ float sh[BDIM];
        float s = 0.0f;
#pragma unroll
        for (int k = 0; k < NB / BDIM; ++k)
            s += d_loss[tid + k * BDIM];
        sh[tid] = s;
        __syncthreads();
        for (int o = BDIM / 2; o > 0; o >>= 1) {
            if (tid < o) sh[tid] += sh[tid + o];
            __syncthreads();
        }
        if (tid == 0) out[0] = sh[0];
    }
}

extern "C" void kernel_launch(void* const* d_in, const int* in_sizes, int n_in,
                              void* d_out, int out_size) {
    const float* x    = (const float*)d_in[0];
    const int*   y    = (const int*)d_in[1];
    const int*   yn   = (const int*)d_in[2];
    const void*  mask = (const void*)d_in[3];
    float*       out  = (float*)d_out;

    init_kernel<<<40, 256>>>();
    detect_kernel<<<64, 256>>>((const unsigned char*)mask);
    build_kernel<<<148, 256>>>(mask);
    loss_kernel<<<NB, BDIM>>>(x, y, yn, out);
}